// round 1
// baseline (speedup 1.0000x reference)
#include <cuda_runtime.h>

// Problem constants (fixed by reference setup_inputs)
#define NB    64
#define NA    5
#define NC    80
#define NH    38
#define NW    38
#define CELLS (NH*NW)          // 1444
#define NBOX  50
#define CH    (5+NC)           // 85
#define BLK   256
#define GX    ((CELLS+BLK-1)/BLK)   // 6
#define NBLOCKS (GX*NB*NA)          // 1920

__constant__ float c_aw[5] = {1.3221f, 3.19275f, 5.05587f, 9.47112f, 11.2364f};
__constant__ float c_ah[5] = {1.73145f, 4.00944f, 8.09892f, 4.84053f, 10.0071f};

__device__ float g_partial[NBLOCKS];

__device__ __forceinline__ float sigmoidf(float x) {
    return 1.0f / (1.0f + expf(-x));
}

__global__ void region_main(const float* __restrict__ out,
                            const float* __restrict__ target) {
    // Per-GT-box data shared across the block (one (b, a) slice per blockIdx.y)
    __shared__ float sx1[NBOX], sx2[NBOX], sy1[NBOX], sy2[NBOX], sarea[NBOX];
    __shared__ float stcx[NBOX], stcy[NBOX], stcw[NBOX], stch[NBOX], scm[NBOX];
    __shared__ int   sfidx[NBOX], scls[NBOX], svalid[NBOX];
    __shared__ int   snv;

    const int ba  = blockIdx.y;       // b*NA + a
    const int b   = ba / NA;
    const int a   = ba - b * NA;
    const int tid = threadIdx.x;

    if (tid < NBOX) {
        const float* tb = target + b * (NBOX * 5) + tid * 5;
        float cls = tb[0], x = tb[1], y = tb[2], w = tb[3], h = tb[4];
        svalid[tid] = (x > 0.0f) ? 1 : 0;
        float gx = x * NW, gy = y * NH, gw = w * NW, gh = h * NH;
        // best anchor by shape IoU (first max wins, matching jnp.argmax)
        int best = 0; float bestv = -1.0f;
        #pragma unroll
        for (int k = 0; k < 5; k++) {
            float aw = c_aw[k], ah = c_ah[k];
            float inter = fminf(aw, gw) * fminf(ah, gh);
            float uni   = aw * ah + gw * gh - inter;
            float v     = inter / fmaxf(uni, 1e-10f);
            if (v > bestv) { bestv = v; best = k; }
        }
        int gi = min(max((int)gx, 0), NW - 1);
        int gj = min(max((int)gy, 0), NH - 1);
        sfidx[tid] = ((b * NA + best) * NH + gj) * NW + gi;
        sx1[tid] = gx - 0.5f * gw;  sx2[tid] = gx + 0.5f * gw;
        sy1[tid] = gy - 0.5f * gh;  sy2[tid] = gy + 0.5f * gh;
        sarea[tid] = gw * gh;
        stcx[tid] = gx - (float)gi;
        stcy[tid] = gy - (float)gj;
        stcw[tid] = logf(gw / c_aw[best]);
        stch[tid] = logf(gh / c_ah[best]);
        scm[tid]  = 2.0f - w * h;
        scls[tid] = (int)cls;
    }
    __syncthreads();
    if (tid == 0) {
        int nv = 0;
        while (nv < NBOX && svalid[nv]) nv++;   // cumprod validity prefix
        snv = nv;
    }
    __syncthreads();
    const int nv = snv;

    float acc = 0.0f;
    const int cell = blockIdx.x * BLK + tid;
    if (cell < CELLS) {
        const int base = (b * (NA * CH) + a * CH) * CELLS + cell;
        float tx = out[base];
        float ty = out[base + CELLS];
        float tw = out[base + 2 * CELLS];
        float th = out[base + 3 * CELLS];
        float to = out[base + 4 * CELLS];

        float sx   = sigmoidf(tx);
        float sy   = sigmoidf(ty);
        float conf = sigmoidf(to);

        const int i = cell % NW, j = cell / NW;
        float px = sx + (float)i, py = sy + (float)j;
        float pw = expf(tw) * c_aw[a], ph = expf(th) * c_ah[a];
        float ax1 = px - 0.5f * pw, ax2 = px + 0.5f * pw;
        float ay1 = py - 0.5f * ph, ay2 = py + 0.5f * ph;
        float parea = pw * ph;

        const int n = ba * CELLS + cell;   // flat prediction index == fidx layout
        bool over = false;
        int  winner = -1;
        for (int t = 0; t < nv; t++) {
            float iw = fminf(ax2, sx2[t]) - fmaxf(ax1, sx1[t]);
            float ih = fminf(ay2, sy2[t]) - fmaxf(ay1, sy1[t]);
            float inter = fmaxf(iw, 0.0f) * fmaxf(ih, 0.0f);
            float uni   = parea + sarea[t] - inter;
            over = over | (inter > 0.6f * uni);     // iou > THRESH, division-free
            if (sfidx[t] == n) winner = t;          // last-write-wins scatter
        }

        float lcoord, lconf, lcls = 0.0f;
        if (winner >= 0) {
            float cm = scm[winner];
            float d0 = (sx - stcx[winner]) * cm;
            float d1 = (sy - stcy[winner]) * cm;
            float d2 = (tw - stcw[winner]) * cm;
            float d3 = (th - stch[winner]) * cm;
            lcoord = d0 * d0 + d1 * d1 + d2 * d2 + d3 * d3;

            // iou(gt, pred at this cell) -> tconf; conf_mask = 5 (obj)
            float iw = fminf(ax2, sx2[winner]) - fmaxf(ax1, sx1[winner]);
            float ih = fminf(ay2, sy2[winner]) - fmaxf(ay1, sy1[winner]);
            float inter = fmaxf(iw, 0.0f) * fmaxf(ih, 0.0f);
            float uni   = parea + sarea[winner] - inter;
            float iou   = inter / fmaxf(uni, 1e-10f);
            float dc = (conf - iou) * 5.0f;
            lconf = dc * dc;

            // class cross-entropy: -log_softmax(logits)[cls]
            const int cb = base + 5 * CELLS;
            float m = -1e30f;
            #pragma unroll 4
            for (int k = 0; k < NC; k++)
                m = fmaxf(m, out[cb + k * CELLS]);
            float s = 0.0f;
            #pragma unroll 4
            for (int k = 0; k < NC; k++)
                s += expf(out[cb + k * CELLS] - m);
            float lc = out[cb + scls[winner] * CELLS];
            lcls = (m + logf(s)) - lc;
        } else {
            // defaults: coord_mask = 0.01, tcoord = (0.5, 0.5, 0, 0) (SEEN < 12800)
            float d0 = (sx - 0.5f) * 0.01f;
            float d1 = (sy - 0.5f) * 0.01f;
            float d2 = tw * 0.01f;
            float d3 = th * 0.01f;
            lcoord = d0 * d0 + d1 * d1 + d2 * d2 + d3 * d3;
            float dc = over ? 0.0f : conf;   // noobj mask 1 iff max_iou <= 0.6
            lconf = dc * dc;
        }
        acc = lcoord + lconf + lcls;
    }

    // deterministic block reduction -> per-block partial
    __shared__ float red[BLK];
    red[tid] = acc;
    __syncthreads();
    for (int s = BLK / 2; s > 0; s >>= 1) {
        if (tid < s) red[tid] += red[tid + s];
        __syncthreads();
    }
    if (tid == 0) g_partial[blockIdx.y * GX + blockIdx.x] = red[0];
}

__global__ void region_reduce(float* __restrict__ outp) {
    __shared__ float red[256];
    float s = 0.0f;
    for (int i = threadIdx.x; i < NBLOCKS; i += 256) s += g_partial[i];
    red[threadIdx.x] = s;
    __syncthreads();
    for (int k = 128; k > 0; k >>= 1) {
        if (threadIdx.x < k) red[threadIdx.x] += red[threadIdx.x + k];
        __syncthreads();
    }
    if (threadIdx.x == 0) outp[0] = red[0] / (float)NB;
}

extern "C" void kernel_launch(void* const* d_in, const int* in_sizes, int n_in,
                              void* d_out, int out_size) {
    const float* output = (const float*)d_in[0];
    const float* target = (const float*)d_in[1];
    float* outp = (float*)d_out;

    dim3 grid(GX, NB * NA);
    region_main<<<grid, BLK>>>(output, target);
    region_reduce<<<1, 256>>>(outp);
}